// round 1
// baseline (speedup 1.0000x reference)
#include <cuda_runtime.h>

// VectorQuantizer: z [16,64,64,64] f32, embed [1024,64] f32
// N = 65536 vectors (b,h,w), C = 64, K = 1024
// out: z_q_st [16,64,64,64] (== gathered codebook rows) + loss scalar at [4194304]

#define K_TOT 1024
#define CDIM  64
#define KC    64        // codes staged per smem chunk
#define TPB   128       // threads per block
#define VPB   256       // vectors per block (2 per thread, packed f32x2)
#define NVEC  65536
#define OUT_Q (NVEC * CDIM)   // 4194304

__device__ float g_loss_acc;

__global__ void vq_zero() { g_loss_acc = 0.0f; }

__device__ __forceinline__ unsigned long long pack2(float x, float y) {
    unsigned long long r;
    asm("mov.b64 %0, {%1,%2};" : "=l"(r) : "f"(x), "f"(y));
    return r;
}
__device__ __forceinline__ void unpack2(unsigned long long v, float &x, float &y) {
    asm("mov.b64 {%0,%1}, %2;" : "=f"(x), "=f"(y) : "l"(v));
}
__device__ __forceinline__ void fma2(unsigned long long &d,
                                     unsigned long long a, unsigned long long b) {
    asm("fma.rn.f32x2 %0, %1, %2, %0;" : "+l"(d) : "l"(a), "l"(b));
}
__device__ __forceinline__ unsigned long long add2(unsigned long long a,
                                                   unsigned long long b) {
    unsigned long long r;
    asm("add.rn.f32x2 %0, %1, %2;" : "=l"(r) : "l"(a), "l"(b));
    return r;
}

__global__ __launch_bounds__(TPB)
void vq_main(const float* __restrict__ z,
             const float* __restrict__ embed,
             float* __restrict__ out)
{
    // codebook chunk, duplicated-interleaved: sdup[k][col] = (e[2c],e[2c],e[2c+1],e[2c+1])
    __shared__ float4 sdup[KC][CDIM / 2];   // 64 * 32 * 16B = 32 KB
    __shared__ float  see[KC];
    __shared__ float  sred[TPB];

    const int t    = threadIdx.x;
    const int base = blockIdx.x * VPB;      // 256 consecutive vectors, within one b
    const int b    = base >> 12;            // / 4096 pixels per image
    const int p0   = (base & 4095) + t;
    const int p1   = p0 + TPB;
    const float* zb = z + ((size_t)b << 18);   // b * C * 4096

    // Load the two owned z vectors into packed registers; compute zz (reference
    // rounding structure: round each square, sequential fp32 adds).
    unsigned long long zr[CDIM];
    float zz0 = 0.0f, zz1 = 0.0f;
#pragma unroll
    for (int c = 0; c < CDIM; ++c) {
        float x = zb[(c << 12) + p0];
        float y = zb[(c << 12) + p1];
        zr[c] = pack2(x, y);
        zz0 = __fadd_rn(zz0, __fmul_rn(x, x));
        zz1 = __fadd_rn(zz1, __fmul_rn(y, y));
    }

    float best0 = 3.4e38f, best1 = 3.4e38f;
    int   idx0  = 0,       idx1  = 0;

    for (int k0 = 0; k0 < K_TOT; k0 += KC) {
        __syncthreads();
        // Stage chunk: conflict-free (consecutive threads -> consecutive cols of a code)
#pragma unroll
        for (int i = t; i < KC * (CDIM / 2); i += TPB) {
            int code = i >> 5;     // / 32 cols
            int col  = i & 31;
            float2 ev = *reinterpret_cast<const float2*>(
                embed + ((size_t)(k0 + code) << 6) + (col << 1));
            sdup[code][col] = make_float4(ev.x, ev.x, ev.y, ev.y);
        }
        if (t < KC) {
            const float* e = embed + ((size_t)(k0 + t) << 6);
            float s = 0.0f;
#pragma unroll
            for (int c = 0; c < CDIM; ++c) s = __fadd_rn(s, __fmul_rn(e[c], e[c]));
            see[t] = s;
        }
        __syncthreads();

#pragma unroll 2
        for (int kk = 0; kk < KC; ++kk) {
            const ulonglong2* sp =
                reinterpret_cast<const ulonglong2*>(&sdup[kk][0]);
            unsigned long long a0 = 0ull, a1 = 0ull, a2 = 0ull, a3 = 0ull;
#pragma unroll
            for (int j = 0; j < 16; ++j) {
                ulonglong2 q0 = sp[2 * j];
                ulonglong2 q1 = sp[2 * j + 1];
                fma2(a0, zr[4 * j + 0], q0.x);
                fma2(a1, zr[4 * j + 1], q0.y);
                fma2(a2, zr[4 * j + 2], q1.x);
                fma2(a3, zr[4 * j + 3], q1.y);
            }
            unsigned long long s01 = add2(add2(a0, a1), add2(a2, a3));
            float d0, d1;
            unpack2(s01, d0, d1);
            float ee = see[kk];
            // replicate reference: dist = fl( fl(zz + ee) - 2*dot )  (2*dot exact)
            float s0 = __fadd_rn(__fadd_rn(zz0, ee), -2.0f * d0);
            float s1 = __fadd_rn(__fadd_rn(zz1, ee), -2.0f * d1);
            int k = k0 + kk;
            if (s0 < best0) { best0 = s0; idx0 = k; }   // strict < : first-index ties
            if (s1 < best1) { best1 = s1; idx1 = k; }
        }
    }

    // Epilogue: gather chosen codes, write z_q_st (== z_q forward), accumulate loss MSE
    const float* e0 = embed + ((size_t)idx0 << 6);
    const float* e1 = embed + ((size_t)idx1 << 6);
    float* ob = out + ((size_t)b << 18);
    float part = 0.0f;
#pragma unroll
    for (int c = 0; c < CDIM; ++c) {
        float x, y;
        unpack2(zr[c], x, y);
        float q0 = e0[c], q1 = e1[c];
        ob[(c << 12) + p0] = q0;
        ob[(c << 12) + p1] = q1;
        float u = q0 - x, v = q1 - y;
        part += u * u + v * v;
    }

    sred[t] = part;
    __syncthreads();
    for (int s = TPB / 2; s > 0; s >>= 1) {
        if (t < s) sred[t] += sred[t + s];
        __syncthreads();
    }
    if (t == 0) atomicAdd(&g_loss_acc, sred[0]);
}

__global__ void vq_finalize(float* out, int out_size) {
    if (threadIdx.x == 0 && out_size > OUT_Q) {
        // loss = mean((zq-z)^2) + 0.25*mean((zq-z)^2) forward
        out[OUT_Q] = 1.25f * g_loss_acc * (1.0f / (float)OUT_Q);
    }
}

extern "C" void kernel_launch(void* const* d_in, const int* in_sizes, int n_in,
                              void* d_out, int out_size) {
    const float* z     = (const float*)d_in[0];
    const float* embed = (const float*)d_in[1];
    float* out = (float*)d_out;

    vq_zero<<<1, 1>>>();
    vq_main<<<NVEC / VPB, TPB>>>(z, embed, out);
    vq_finalize<<<1, 32>>>(out, out_size);
}

// round 3
// speedup vs baseline: 2.1177x; 2.1177x over previous
#include <cuda_runtime.h>

// VectorQuantizer: z [16,64,64,64] f32, embed [1024,64] f32
// N = 65536 pixel-vectors, C = 64, K = 1024
// out[0..4194303] = z_q_st (gathered codebook rows), out[4194304] = loss

#define CDIM   64
#define TPB    256
#define PXB    256         // pixels per CTA
#define NPX    65536
#define OUT_Q  4194304
#define ROUNDS 16          // 1024 codes / (8 warps * 8 codes)

// shared memory byte offsets
#define SM_ZS   0                       // float  zs[64][256]   = 65536 B
#define SM_ESD  65536                   // u64   esd[64][64]    = 32768 B (dup pairs)
#define SM_SZZ  (65536 + 32768)         // float szz[256]       = 1024 B
#define SM_SEE  (SM_SZZ + 1024)         // float see[64]        = 256 B
#define SM_LRED (SM_SEE + 256)          // float lred[256]      = 1024 B
#define SM_TOT  (SM_LRED + 1024)        // 100608 B

__device__ __forceinline__ unsigned long long pack2(float x, float y) {
    unsigned long long r;
    asm("mov.b64 %0, {%1,%2};" : "=l"(r) : "f"(x), "f"(y));
    return r;
}
__device__ __forceinline__ void unpack2(unsigned long long v, float &x, float &y) {
    asm("mov.b64 {%0,%1}, %2;" : "=f"(x), "=f"(y) : "l"(v));
}
__device__ __forceinline__ void fma2(unsigned long long &d,
                                     unsigned long long a, unsigned long long b) {
    asm("fma.rn.f32x2 %0, %1, %2, %0;" : "+l"(d) : "l"(a), "l"(b));
}

__global__ void vq_zero(float* out, int out_size) {
    if (out_size > OUT_Q) out[OUT_Q] = 0.0f;
}

__global__ __launch_bounds__(TPB, 2)
void vq_main(const float* __restrict__ z,
             const float* __restrict__ embed,
             float* __restrict__ out, int out_size)
{
    extern __shared__ unsigned char smem[];
    float* zs  = (float*)(smem + SM_ZS);                       // [64][256]
    unsigned long long* esd = (unsigned long long*)(smem + SM_ESD); // [64][64]
    float* szz = (float*)(smem + SM_SZZ);
    float* see = (float*)(smem + SM_SEE);
    float* lred = (float*)(smem + SM_LRED);

    const int t    = threadIdx.x;
    const int lane = t & 31;
    const int ty   = t >> 5;               // warp id = code slice
    const int base = blockIdx.x * PXB;
    const int b    = base >> 12;
    const int p0   = base & 4095;
    const float* zb = z + ((size_t)b << 18);

    // ---- load z tile (coalesced) + per-pixel zz (reference rounding: seq adds) ----
    float zz_acc = 0.0f;
#pragma unroll
    for (int c = 0; c < CDIM; ++c) {
        float v = zb[(c << 12) + p0 + t];
        zs[c * 256 + t] = v;
        zz_acc = __fadd_rn(zz_acc, __fmul_rn(v, v));
    }
    szz[t] = zz_acc;
    __syncthreads();

    // my 8 pixels: indices 8*lane .. 8*lane+7 (same for every warp)
    float zz[8];
#pragma unroll
    for (int i = 0; i < 8; ++i) zz[i] = szz[lane * 8 + i];

    float bd[8];
    int   bi[8];
#pragma unroll
    for (int i = 0; i < 8; ++i) { bd[i] = 3.4e38f; bi[i] = 0; }

    const int kslice = ty * 128;
    const char* zp0 = (const char*)(zs + lane * 8);        // +c*1024 per step
    const char* ep0 = (const char*)(esd + ty * 8);         // +c*512  per step

    for (int r = 0; r < ROUNDS; ++r) {
        __syncthreads();   // previous round's esd consumers are done

        // ---- stage 64 codes (8 per slice) as duplicated pairs, c-major ----
        {
            const int q  = t >> 2;                 // 0..63 staged-code column
            const int c0 = (t & 3) << 4;           // 16-c chunk
            const int k  = (q >> 3) * 128 + r * 8 + (q & 7);
            const float4* ev = (const float4*)(embed + (k << 6) + c0);
#pragma unroll
            for (int i = 0; i < 4; ++i) {
                float4 v = ev[i];
                int c = c0 + i * 4;
                esd[(c + 0) * 64 + q] = pack2(v.x, v.x);
                esd[(c + 1) * 64 + q] = pack2(v.y, v.y);
                esd[(c + 2) * 64 + q] = pack2(v.z, v.z);
                esd[(c + 3) * 64 + q] = pack2(v.w, v.w);
            }
        }
        if (t < 64) {   // ee for the 64 staged codes (reference rounding)
            const int k = (t >> 3) * 128 + r * 8 + (t & 7);
            const float* e = embed + (k << 6);
            float s = 0.0f;
#pragma unroll
            for (int c = 0; c < CDIM; ++c) s = __fadd_rn(s, __fmul_rn(e[c], e[c]));
            see[t] = s;
        }
        __syncthreads();

        // ---- 8 codes x 8 pixels register tile, f32x2 accumulation ----
        unsigned long long acc[8][4];
#pragma unroll
        for (int j = 0; j < 8; ++j)
#pragma unroll
            for (int pp = 0; pp < 4; ++pp) acc[j][pp] = 0ull;

#pragma unroll 2
        for (int c = 0; c < CDIM; ++c) {
            const ulonglong2* zc = (const ulonglong2*)(zp0 + c * 1024);
            ulonglong2 za = zc[0];    // px pairs 0,1
            ulonglong2 zb2 = zc[1];   // px pairs 2,3
            const ulonglong2* ec = (const ulonglong2*)(ep0 + c * 512);
            ulonglong2 e0 = ec[0], e1 = ec[1], e2 = ec[2], e3 = ec[3];
#define FMJ(j, ed) \
            fma2(acc[j][0], za.x,  ed); fma2(acc[j][1], za.y,  ed); \
            fma2(acc[j][2], zb2.x, ed); fma2(acc[j][3], zb2.y, ed);
            FMJ(0, e0.x) FMJ(1, e0.y) FMJ(2, e1.x) FMJ(3, e1.y)
            FMJ(4, e2.x) FMJ(5, e2.y) FMJ(6, e3.x) FMJ(7, e3.y)
#undef FMJ
        }

        // ---- fold into running argmin (ascending k, strict < => first-index ties) ----
#pragma unroll
        for (int j = 0; j < 8; ++j) {
            float ee = see[ty * 8 + j];
            int k = kslice + r * 8 + j;
#pragma unroll
            for (int pp = 0; pp < 4; ++pp) {
                float d0, d1;
                unpack2(acc[j][pp], d0, d1);
                // reference rounding: fl( fl(zz+ee) - 2*dot )
                float s0 = __fadd_rn(__fadd_rn(zz[2 * pp],     ee), -2.0f * d0);
                float s1 = __fadd_rn(__fadd_rn(zz[2 * pp + 1], ee), -2.0f * d1);
                if (s0 < bd[2 * pp])     { bd[2 * pp]     = s0; bi[2 * pp]     = k; }
                if (s1 < bd[2 * pp + 1]) { bd[2 * pp + 1] = s1; bi[2 * pp + 1] = k; }
            }
        }
    }

    // ---- cross-warp argmin reduction (slices ascending with ty; strict <) ----
    __syncthreads();
    float* red_d = (float*)(smem + SM_ESD);              // [8][256], overlays esd
    int*   red_i = (int*)(smem + SM_ESD + 8192);         // [8][256]
#pragma unroll
    for (int i = 0; i < 8; ++i) {
        red_d[ty * 256 + lane * 8 + i] = bd[i];
        red_i[ty * 256 + lane * 8 + i] = bi[i];
    }
    __syncthreads();

    float bestd = red_d[t];
    int   bestk = red_i[t];
#pragma unroll
    for (int w = 1; w < 8; ++w) {
        float d = red_d[w * 256 + t];
        int   k = red_i[w * 256 + t];
        if (d < bestd) { bestd = d; bestk = k; }
    }

    // ---- gather, write z_q_st, loss partial ----
    const float4* er4 = (const float4*)(embed + (bestk << 6));
    float* ob = out + ((size_t)b << 18);
    float lpart = 0.0f;
#pragma unroll
    for (int i = 0; i < 16; ++i) {
        float4 v = er4[i];
        int c = i * 4;
        float q0 = v.x, q1 = v.y, q2 = v.z, q3 = v.w;
        float z0 = zs[(c + 0) * 256 + t];
        float z1 = zs[(c + 1) * 256 + t];
        float z2 = zs[(c + 2) * 256 + t];
        float z3 = zs[(c + 3) * 256 + t];
        ob[((c + 0) << 12) + p0 + t] = q0;
        ob[((c + 1) << 12) + p0 + t] = q1;
        ob[((c + 2) << 12) + p0 + t] = q2;
        ob[((c + 3) << 12) + p0 + t] = q3;
        float d0 = q0 - z0, d1 = q1 - z1, d2 = q2 - z2, d3 = q3 - z3;
        lpart += d0 * d0 + d1 * d1 + d2 * d2 + d3 * d3;
    }

    lred[t] = lpart;
    __syncthreads();
    for (int s = TPB / 2; s > 0; s >>= 1) {
        if (t < s) lred[t] += lred[t + s];
        __syncthreads();
    }
    if (t == 0 && out_size > OUT_Q) {
        // loss = (1 + 0.25) * mean((z_q - z)^2) in forward
        atomicAdd(&out[OUT_Q], lred[0] * (1.25f / (float)OUT_Q));
    }
}

extern "C" void kernel_launch(void* const* d_in, const int* in_sizes, int n_in,
                              void* d_out, int out_size) {
    const float* z     = (const float*)d_in[0];
    const float* embed = (const float*)d_in[1];
    float* out = (float*)d_out;

    static int configured = 0;
    if (!configured) {
        cudaFuncSetAttribute(vq_main, cudaFuncAttributeMaxDynamicSharedMemorySize, SM_TOT);
        configured = 1;
    }

    vq_zero<<<1, 32>>>(out, out_size);
    vq_main<<<NPX / PXB, TPB, SM_TOT>>>(z, embed, out, out_size);
}

// round 6
// speedup vs baseline: 5.0037x; 2.3628x over previous
#include <cuda_runtime.h>
#include <cuda_fp16.h>
#include <cstdint>

// VectorQuantizer via mma.sync (HMMA) fp16 2x2 split-GEMM.
// z [16,64,64,64] f32, embed [1024,64] f32.
// out[0..4194303] = z_q_st, out[4194304] = loss.

#define CDIM   64
#define NPX    65536
#define OUT_Q  4194304
#define KTOT   1024
#define TPB    256
#define MPX    128         // pixels per CTA
#define CHK    128         // codes per chunk
#define NCHUNK 8
#define NGRP   16          // 8-code groups per chunk
#define ROWB   144         // padded row bytes (64 halves + 8 pad) -> conflict-free ldmatrix

// ---- smem byte offsets ----
#define SM_ZH   0                         // [128 px][72 halves]  18432
#define SM_ZL   18432
#define SM_EH   36864                     // [128 codes][72 halves]
#define SM_EL   55296
#define SM_ZF   73728                     // [64 c][128 px] f32   32768
#define SM_EE   106496                    // [1024] f32
#define SM_ZZ   110592                    // [128] f32
#define SM_IDX  111104                    // [128] int
#define SM_RED  111616                    // [256] f32
#define SM_TOT  112640

__device__ uint4 g_ebh[KTOT * 8];   // fp16(1024*e)  [1024][64] halves
__device__ uint4 g_ebl[KTOT * 8];   // fp16 residual
__device__ float g_ee[KTOT];

__device__ __forceinline__ uint32_t smem_u32(const void* p) {
    uint32_t a;
    asm("{ .reg .u64 t; cvta.to.shared.u64 t, %1; cvt.u32.u64 %0, t; }"
        : "=r"(a) : "l"(p));
    return a;
}
__device__ __forceinline__ void ldsm4(uint32_t& r0, uint32_t& r1, uint32_t& r2,
                                      uint32_t& r3, uint32_t addr) {
    asm volatile("ldmatrix.sync.aligned.m8n8.x4.shared.b16 {%0,%1,%2,%3}, [%4];"
                 : "=r"(r0), "=r"(r1), "=r"(r2), "=r"(r3) : "r"(addr));
}
__device__ __forceinline__ void mma16816(float& d0, float& d1, float& d2, float& d3,
                                         uint32_t a0, uint32_t a1, uint32_t a2,
                                         uint32_t a3, uint32_t b0, uint32_t b1) {
    asm volatile(
        "mma.sync.aligned.m16n8k16.row.col.f32.f16.f16.f32 "
        "{%0,%1,%2,%3}, {%4,%5,%6,%7}, {%8,%9}, {%0,%1,%2,%3};"
        : "+f"(d0), "+f"(d1), "+f"(d2), "+f"(d3)
        : "r"(a0), "r"(a1), "r"(a2), "r"(a3), "r"(b0), "r"(b1));
}
__device__ __forceinline__ void amerge(float& d, int& i, float d2, int i2) {
    if (d2 < d || (d2 == d && i2 < i)) { d = d2; i = i2; }
}

// ---------------- precompute: split codebook, ee ----------------
__global__ void vq_pre(const float* __restrict__ embed, float* out, int out_size) {
    int k = blockIdx.x * blockDim.x + threadIdx.x;
    if (k == 0 && out_size > OUT_Q) out[OUT_Q] = 0.0f;
    if (k >= KTOT) return;
    const float* e = embed + k * CDIM;
    __half2* eh = (__half2*)g_ebh;
    __half2* el = (__half2*)g_ebl;
    float s = 0.0f;
#pragma unroll
    for (int c = 0; c < CDIM; c += 2) {
        float v0 = e[c], v1 = e[c + 1];
        s = __fadd_rn(s, __fmul_rn(v0, v0));
        s = __fadd_rn(s, __fmul_rn(v1, v1));
        float w0 = v0 * 1024.0f, w1 = v1 * 1024.0f;   // exact scaling
        __half h0 = __float2half_rn(w0);
        __half h1 = __float2half_rn(w1);
        __half l0 = __float2half_rn(w0 - __half2float(h0));
        __half l1 = __float2half_rn(w1 - __half2float(h1));
        eh[k * 32 + (c >> 1)] = __halves2half2(h0, h1);
        el[k * 32 + (c >> 1)] = __halves2half2(l0, l1);
    }
    g_ee[k] = s;
}

// ---------------- main kernel ----------------
__global__ __launch_bounds__(TPB, 2)
void vq_main(const float* __restrict__ z,
             const float* __restrict__ embed,
             float* __restrict__ out, int out_size)
{
    extern __shared__ unsigned char smem[];
    const uint32_t sb = smem_u32(smem);
    float* zf  = (float*)(smem + SM_ZF);
    float* ee  = (float*)(smem + SM_EE);
    float* szz = (float*)(smem + SM_ZZ);
    int*   sidx = (int*)(smem + SM_IDX);
    float* red = (float*)(smem + SM_RED);

    const int t    = threadIdx.x;
    const int lane = t & 31;
    const int w    = t >> 5;              // warp 0..7: rows w*16..w*16+15

    const int base = blockIdx.x * MPX;
    const int b    = base >> 12;
    const int po   = base & 4095;
    const float* zb = z + ((size_t)b << 18) + po;

    // ---- load z tile (coalesced) + ee ----
#pragma unroll
    for (int j = 0; j < 32; ++j) {
        int i = t + j * 256;
        int c = i >> 7, px = i & 127;
        zf[c * 128 + px] = zb[(c << 12) + px];
    }
#pragma unroll
    for (int j = 0; j < 4; ++j) ee[t + j * 256] = g_ee[t + j * 256];
    __syncthreads();

    // ---- zz per pixel (reference rounding: sequential fp32) ----
    if (t < 128) {
        float s = 0.0f;
#pragma unroll
        for (int c = 0; c < CDIM; ++c) {
            float v = zf[c * 128 + t];
            s = __fadd_rn(s, __fmul_rn(v, v));
        }
        szz[t] = s;
    }

    // ---- split z into zh/zl fp16 tiles [px][72] ----
    {
        __half* zhp = (__half*)(smem + SM_ZH);
        __half* zlp = (__half*)(smem + SM_ZL);
#pragma unroll
        for (int j = 0; j < 32; ++j) {
            int i = t + j * 256;
            int c = i >> 7, px = i & 127;
            float v = zf[c * 128 + px];
            __half h = __float2half_rn(v);
            __half l = __float2half_rn(v - __half2float(h));
            zhp[px * 72 + c] = h;
            zlp[px * 72 + c] = l;
        }
    }
    __syncthreads();

    // ---- A fragments (register resident): 4 ksteps x {zh, zl} ----
    uint32_t aH[4][4], aL[4][4];
    {
        const int m    = lane >> 3;
        const int arow = w * 16 + (m & 1) * 8 + (lane & 7);
        const int coff = (m >> 1) * 16;   // bytes: (m>>1)*8 halves
        uint32_t adH = sb + SM_ZH + arow * ROWB + coff;
        uint32_t adL = sb + SM_ZL + arow * ROWB + coff;
#pragma unroll
        for (int ks = 0; ks < 4; ++ks) {
            ldsm4(aH[ks][0], aH[ks][1], aH[ks][2], aH[ks][3], adH + ks * 32);
            ldsm4(aL[ks][0], aL[ks][1], aL[ks][2], aL[ks][3], adL + ks * 32);
        }
    }

    const float zzr0 = szz[w * 16 + (lane >> 2)];
    const float zzr8 = szz[w * 16 + 8 + (lane >> 2)];

    float bd0 = 3.4e38f, bd1 = 3.4e38f, bd2 = 3.4e38f, bd3 = 3.4e38f;
    int   bi0 = 0, bi1 = 0, bi2 = 0, bi3 = 0;

    const uint32_t bH0 = sb + SM_EH + (lane & 7) * ROWB + (lane >> 3) * 16;
    const uint32_t bL0 = sb + SM_EL + (lane & 7) * ROWB + (lane >> 3) * 16;
    const int cql = 2 * (lane & 3);

    for (int ch = 0; ch < NCHUNK; ++ch) {
        // ---- stage 128-code chunk: eh/el, padded rows ----
        {
            const uint4* srcH = g_ebh + (ch * CHK) * 8;
            const uint4* srcL = g_ebl + (ch * CHK) * 8;
            unsigned char* dH = smem + SM_EH;
            unsigned char* dL = smem + SM_EL;
#pragma unroll
            for (int j = 0; j < 4; ++j) {
                int i = t + j * 256;           // 1024 uint4 per tier
                int row = i >> 3, q = i & 7;
                *(uint4*)(dH + row * ROWB + q * 16) = srcH[i];
                *(uint4*)(dL + row * ROWB + q * 16) = srcL[i];
            }
        }
        __syncthreads();

#pragma unroll 1
        for (int g = 0; g < NGRP; ++g) {
            const uint32_t bo = (uint32_t)(g * 8 * ROWB);
            uint32_t bh[8], bl[8];
            ldsm4(bh[0], bh[1], bh[2], bh[3], bH0 + bo);
            ldsm4(bh[4], bh[5], bh[6], bh[7], bH0 + bo + 64);
            ldsm4(bl[0], bl[1], bl[2], bl[3], bL0 + bo);
            ldsm4(bl[4], bl[5], bl[6], bl[7], bL0 + bo + 64);

            float d0 = 0.f, d1 = 0.f, d2 = 0.f, d3 = 0.f;
#pragma unroll
            for (int ks = 0; ks < 4; ++ks) {
                mma16816(d0, d1, d2, d3, aH[ks][0], aH[ks][1], aH[ks][2], aH[ks][3],
                         bh[2 * ks], bh[2 * ks + 1]);
                mma16816(d0, d1, d2, d3, aH[ks][0], aH[ks][1], aH[ks][2], aH[ks][3],
                         bl[2 * ks], bl[2 * ks + 1]);
                mma16816(d0, d1, d2, d3, aL[ks][0], aL[ks][1], aL[ks][2], aL[ks][3],
                         bh[2 * ks], bh[2 * ks + 1]);
                mma16816(d0, d1, d2, d3, aL[ks][0], aL[ks][1], aL[ks][2], aL[ks][3],
                         bl[2 * ks], bl[2 * ks + 1]);
            }

            // fold: s = fl( fl(zz+ee) - dot'/512 ),  dot' = 1024*dot
            const int k0 = ch * CHK + g * 8 + cql;
            const float e0 = ee[k0], e1 = ee[k0 + 1];
            float s;
            s = __fmaf_rn(-(1.0f / 512.0f), d0, __fadd_rn(zzr0, e0));
            if (s < bd0) { bd0 = s; bi0 = k0; }
            s = __fmaf_rn(-(1.0f / 512.0f), d1, __fadd_rn(zzr0, e1));
            if (s < bd1) { bd1 = s; bi1 = k0 + 1; }
            s = __fmaf_rn(-(1.0f / 512.0f), d2, __fadd_rn(zzr8, e0));
            if (s < bd2) { bd2 = s; bi2 = k0; }
            s = __fmaf_rn(-(1.0f / 512.0f), d3, __fadd_rn(zzr8, e1));
            if (s < bd3) { bd3 = s; bi3 = k0 + 1; }
        }
        __syncthreads();   // before next chunk overwrites eh/el
    }

    // ---- reduce: in-lane col pair, then quad (lanes share a row) ----
    amerge(bd0, bi0, bd1, bi1);         // row r
    amerge(bd2, bi2, bd3, bi3);         // row r+8
#pragma unroll
    for (int x = 1; x <= 2; x <<= 1) {
        float od = __shfl_xor_sync(0xffffffff, bd0, x);
        int   oi = __shfl_xor_sync(0xffffffff, bi0, x);
        amerge(bd0, bi0, od, oi);
        od = __shfl_xor_sync(0xffffffff, bd2, x);
        oi = __shfl_xor_sync(0xffffffff, bi2, x);
        amerge(bd2, bi2, od, oi);
    }
    if ((lane & 3) == 0) {
        sidx[w * 16 + (lane >> 2)]     = bi0;
        sidx[w * 16 + 8 + (lane >> 2)] = bi2;
    }
    __syncthreads();

    // ---- epilogue: gather, straight-through (bit-exact), loss ----
    float* ob = out + ((size_t)b << 18) + po;
    float lp = 0.0f;
#pragma unroll
    for (int j = 0; j < 32; ++j) {
        int i = t + j * 256;
        int c = i >> 7, px = i & 127;
        float q  = embed[sidx[px] * CDIM + c];
        float zv = zf[c * 128 + px];
        float d  = __fadd_rn(q, -zv);            // fl(z_q - z)
        ob[(c << 12) + px] = __fadd_rn(zv, d);   // fl(z + fl(z_q - z))
        lp += d * d;
    }
    red[t] = lp;
    __syncthreads();
    for (int s = TPB / 2; s > 0; s >>= 1) {
        if (t < s) red[t] += red[t + s];
        __syncthreads();
    }
    if (t == 0 && out_size > OUT_Q)
        atomicAdd(&out[OUT_Q], red[0] * (1.25f / (float)OUT_Q));
}

extern "C" void kernel_launch(void* const* d_in, const int* in_sizes, int n_in,
                              void* d_out, int out_size) {
    const float* z     = (const float*)d_in[0];
    const float* embed = (const float*)d_in[1];
    float* out = (float*)d_out;

    static int configured = 0;
    if (!configured) {
        cudaFuncSetAttribute(vq_main, cudaFuncAttributeMaxDynamicSharedMemorySize,
                             SM_TOT);
        configured = 1;
    }

    vq_pre<<<4, 256>>>(embed, out, out_size);
    vq_main<<<NPX / MPX, TPB, SM_TOT>>>(z, embed, out, out_size);
}

// round 7
// speedup vs baseline: 5.5691x; 1.1130x over previous
#include <cuda_runtime.h>
#include <cuda_fp16.h>
#include <cstdint>

// VectorQuantizer via mma.sync (HMMA) fp16 3-product split-GEMM,
// double-buffered cp.async staging.
// z [16,64,64,64] f32, embed [1024,64] f32.
// out[0..4194303] = z_q_st, out[4194304] = loss.

#define CDIM   64
#define NPX    65536
#define OUT_Q  4194304
#define KTOT   1024
#define TPB    256
#define MPX    128         // pixels per CTA
#define CHK    64          // codes per chunk (double-buffered)
#define NCHUNK 16
#define NGRP   8           // 8-code groups per chunk
#define ROWB   144         // padded row bytes -> conflict-free ldmatrix

// ---- smem byte offsets ----
#define SM_ZH   0                         // [128 px][72 halves] 18432
#define SM_ZL   18432
#define SM_EB   36864                     // 2 bufs x {EH 9216, EL 9216} = 36864
#define SM_ZF   73728                     // [64 c][128 px] f32  32768
#define SM_EE   106496                    // [1024] f32
#define SM_ZZ   110592                    // [128] f32
#define SM_IDX  111104                    // [128] int
#define SM_RED  111616                    // [256] f32
#define SM_TOT  112640
#define EBUF(buf) (SM_EB + (buf) * 18432)

__device__ uint4 g_ebh[KTOT * 8];   // fp16(1024*e)  [1024][64] halves
__device__ uint4 g_ebl[KTOT * 8];   // fp16 residual
__device__ float g_ee[KTOT];

__device__ __forceinline__ uint32_t smem_u32(const void* p) {
    uint32_t a;
    asm("{ .reg .u64 t; cvta.to.shared.u64 t, %1; cvt.u32.u64 %0, t; }"
        : "=r"(a) : "l"(p));
    return a;
}
__device__ __forceinline__ void ldsm4(uint32_t& r0, uint32_t& r1, uint32_t& r2,
                                      uint32_t& r3, uint32_t addr) {
    asm volatile("ldmatrix.sync.aligned.m8n8.x4.shared.b16 {%0,%1,%2,%3}, [%4];"
                 : "=r"(r0), "=r"(r1), "=r"(r2), "=r"(r3) : "r"(addr));
}
__device__ __forceinline__ void mma16816(float& d0, float& d1, float& d2, float& d3,
                                         uint32_t a0, uint32_t a1, uint32_t a2,
                                         uint32_t a3, uint32_t b0, uint32_t b1) {
    asm volatile(
        "mma.sync.aligned.m16n8k16.row.col.f32.f16.f16.f32 "
        "{%0,%1,%2,%3}, {%4,%5,%6,%7}, {%8,%9}, {%0,%1,%2,%3};"
        : "+f"(d0), "+f"(d1), "+f"(d2), "+f"(d3)
        : "r"(a0), "r"(a1), "r"(a2), "r"(a3), "r"(b0), "r"(b1));
}
__device__ __forceinline__ void amerge(float& d, int& i, float d2, int i2) {
    if (d2 < d || (d2 == d && i2 < i)) { d = d2; i = i2; }
}
#define CPA16(s, g) \
    asm volatile("cp.async.cg.shared.global [%0], [%1], 16;" \
                 :: "r"(s), "l"(g) : "memory")
#define CPA_COMMIT() asm volatile("cp.async.commit_group;" ::: "memory")
#define CPA_WAIT0()  asm volatile("cp.async.wait_group 0;" ::: "memory")

// ---------------- precompute: split codebook, ee ----------------
__global__ void vq_pre(const float* __restrict__ embed, float* out, int out_size) {
    int k = blockIdx.x * blockDim.x + threadIdx.x;
    if (k == 0 && out_size > OUT_Q) out[OUT_Q] = 0.0f;
    if (k >= KTOT) return;
    const float* e = embed + k * CDIM;
    __half2* eh = (__half2*)g_ebh;
    __half2* el = (__half2*)g_ebl;
    float s = 0.0f;
#pragma unroll
    for (int c = 0; c < CDIM; c += 2) {
        float v0 = e[c], v1 = e[c + 1];
        s = __fadd_rn(s, __fmul_rn(v0, v0));
        s = __fadd_rn(s, __fmul_rn(v1, v1));
        float w0 = v0 * 1024.0f, w1 = v1 * 1024.0f;   // exact scaling
        __half h0 = __float2half_rn(w0);
        __half h1 = __float2half_rn(w1);
        __half l0 = __float2half_rn(w0 - __half2float(h0));
        __half l1 = __float2half_rn(w1 - __half2float(h1));
        eh[k * 32 + (c >> 1)] = __halves2half2(h0, h1);
        el[k * 32 + (c >> 1)] = __halves2half2(l0, l1);
    }
    g_ee[k] = s;
}

// ---------------- main kernel ----------------
__global__ __launch_bounds__(TPB, 2)
void vq_main(const float* __restrict__ z,
             const float* __restrict__ embed,
             float* __restrict__ out, int out_size)
{
    extern __shared__ unsigned char smem[];
    const uint32_t sb = smem_u32(smem);
    float* zf  = (float*)(smem + SM_ZF);
    float* ee  = (float*)(smem + SM_EE);
    float* szz = (float*)(smem + SM_ZZ);
    int*   sidx = (int*)(smem + SM_IDX);
    float* red = (float*)(smem + SM_RED);

    const int t    = threadIdx.x;
    const int lane = t & 31;
    const int w    = t >> 5;              // warp 0..7: rows w*16..w*16+15

    const int base = blockIdx.x * MPX;
    const int b    = base >> 12;
    const int po   = base & 4095;
    const float* zb = z + ((size_t)b << 18) + po;

    // ---- stage chunk 0 immediately (overlap with z-tile work) ----
    {
        const uint4* srcH = g_ebh;
        const uint4* srcL = g_ebl;
#pragma unroll
        for (int j = 0; j < 2; ++j) {
            int i = t + j * 256;               // 512 uint4 per tier
            int row = i >> 3, q = i & 7;
            uint32_t off = (uint32_t)(row * ROWB + q * 16);
            CPA16(sb + EBUF(0) + off,        srcH + i);
            CPA16(sb + EBUF(0) + 9216 + off, srcL + i);
        }
        CPA_COMMIT();
    }

    // ---- load z tile (coalesced) + ee ----
#pragma unroll
    for (int j = 0; j < 32; ++j) {
        int i = t + j * 256;
        int c = i >> 7, px = i & 127;
        zf[c * 128 + px] = zb[(c << 12) + px];
    }
#pragma unroll
    for (int j = 0; j < 4; ++j) ee[t + j * 256] = g_ee[t + j * 256];
    __syncthreads();

    // ---- zz per pixel (reference rounding: sequential fp32) ----
    if (t < 128) {
        float s = 0.0f;
#pragma unroll
        for (int c = 0; c < CDIM; ++c) {
            float v = zf[c * 128 + t];
            s = __fadd_rn(s, __fmul_rn(v, v));
        }
        szz[t] = s;
    }

    // ---- split z into zh/zl fp16 tiles [px][72] ----
    {
        __half* zhp = (__half*)(smem + SM_ZH);
        __half* zlp = (__half*)(smem + SM_ZL);
#pragma unroll
        for (int j = 0; j < 32; ++j) {
            int i = t + j * 256;
            int c = i >> 7, px = i & 127;
            float v = zf[c * 128 + px];
            __half h = __float2half_rn(v);
            __half l = __float2half_rn(v - __half2float(h));
            zhp[px * 72 + c] = h;
            zlp[px * 72 + c] = l;
        }
    }
    __syncthreads();

    // ---- A fragments (register resident): 4 ksteps x {zh, zl} ----
    uint32_t aH[4][4], aL[4][4];
    {
        const int m    = lane >> 3;
        const int arow = w * 16 + (m & 1) * 8 + (lane & 7);
        const int coff = (m >> 1) * 16;
        uint32_t adH = sb + SM_ZH + arow * ROWB + coff;
        uint32_t adL = sb + SM_ZL + arow * ROWB + coff;
#pragma unroll
        for (int ks = 0; ks < 4; ++ks) {
            ldsm4(aH[ks][0], aH[ks][1], aH[ks][2], aH[ks][3], adH + ks * 32);
            ldsm4(aL[ks][0], aL[ks][1], aL[ks][2], aL[ks][3], adL + ks * 32);
        }
    }

    const float zzr0 = szz[w * 16 + (lane >> 2)];
    const float zzr8 = szz[w * 16 + 8 + (lane >> 2)];

    float bd0 = 3.4e38f, bd1 = 3.4e38f, bd2 = 3.4e38f, bd3 = 3.4e38f;
    int   bi0 = 0, bi1 = 0, bi2 = 0, bi3 = 0;

    const uint32_t blane = (lane & 7) * ROWB + (lane >> 3) * 16;
    const int cql = 2 * (lane & 3);

    for (int ch = 0; ch < NCHUNK; ++ch) {
        const int buf = ch & 1;
        CPA_WAIT0();          // current buffer filled
        __syncthreads();      // all warps done with the other buffer

        // prefetch chunk ch+1 into the other buffer (hidden under compute)
        if (ch + 1 < NCHUNK) {
            const uint4* srcH = g_ebh + (ch + 1) * CHK * 8;
            const uint4* srcL = g_ebl + (ch + 1) * CHK * 8;
            const uint32_t db = sb + EBUF(buf ^ 1);
#pragma unroll
            for (int j = 0; j < 2; ++j) {
                int i = t + j * 256;
                int row = i >> 3, q = i & 7;
                uint32_t off = (uint32_t)(row * ROWB + q * 16);
                CPA16(db + off,        srcH + i);
                CPA16(db + 9216 + off, srcL + i);
            }
            CPA_COMMIT();
        }

        const uint32_t bH0 = sb + EBUF(buf) + blane;
        const uint32_t bL0 = bH0 + 9216;

        // ---- group loop with B-register double buffering ----
        uint32_t bh[2][8], bl[2][8];
        ldsm4(bh[0][0], bh[0][1], bh[0][2], bh[0][3], bH0);
        ldsm4(bh[0][4], bh[0][5], bh[0][6], bh[0][7], bH0 + 64);
        ldsm4(bl[0][0], bl[0][1], bl[0][2], bl[0][3], bL0);
        ldsm4(bl[0][4], bl[0][5], bl[0][6], bl[0][7], bL0 + 64);

#pragma unroll
        for (int g = 0; g < NGRP; ++g) {
            const int cur = g & 1, nxt = cur ^ 1;
            if (g + 1 < NGRP) {
                const uint32_t bo = (uint32_t)((g + 1) * 8 * ROWB);
                ldsm4(bh[nxt][0], bh[nxt][1], bh[nxt][2], bh[nxt][3], bH0 + bo);
                ldsm4(bh[nxt][4], bh[nxt][5], bh[nxt][6], bh[nxt][7], bH0 + bo + 64);
                ldsm4(bl[nxt][0], bl[nxt][1], bl[nxt][2], bl[nxt][3], bL0 + bo);
                ldsm4(bl[nxt][4], bl[nxt][5], bl[nxt][6], bl[nxt][7], bL0 + bo + 64);
            }

            // 12 MMAs: accP (8-chain, eh) + accQ (4-chain, el)
            float p0 = 0.f, p1 = 0.f, p2 = 0.f, p3 = 0.f;
            float q0 = 0.f, q1 = 0.f, q2 = 0.f, q3 = 0.f;
#pragma unroll
            for (int ks = 0; ks < 4; ++ks) {
                mma16816(p0, p1, p2, p3, aH[ks][0], aH[ks][1], aH[ks][2], aH[ks][3],
                         bh[cur][2 * ks], bh[cur][2 * ks + 1]);
                mma16816(q0, q1, q2, q3, aH[ks][0], aH[ks][1], aH[ks][2], aH[ks][3],
                         bl[cur][2 * ks], bl[cur][2 * ks + 1]);
            }
#pragma unroll
            for (int ks = 0; ks < 4; ++ks) {
                mma16816(p0, p1, p2, p3, aL[ks][0], aL[ks][1], aL[ks][2], aL[ks][3],
                         bh[cur][2 * ks], bh[cur][2 * ks + 1]);
            }
            const float d0 = p0 + q0, d1 = p1 + q1;
            const float d2 = p2 + q2, d3 = p3 + q3;

            // fold: s = fl( fl(zz+ee) - dot'/512 ),  dot' = 1024*dot
            const int k0 = ch * CHK + g * 8 + cql;
            const float e0 = ee[k0], e1 = ee[k0 + 1];
            float s;
            s = __fmaf_rn(-(1.0f / 512.0f), d0, __fadd_rn(zzr0, e0));
            if (s < bd0) { bd0 = s; bi0 = k0; }
            s = __fmaf_rn(-(1.0f / 512.0f), d1, __fadd_rn(zzr0, e1));
            if (s < bd1) { bd1 = s; bi1 = k0 + 1; }
            s = __fmaf_rn(-(1.0f / 512.0f), d2, __fadd_rn(zzr8, e0));
            if (s < bd2) { bd2 = s; bi2 = k0; }
            s = __fmaf_rn(-(1.0f / 512.0f), d3, __fadd_rn(zzr8, e1));
            if (s < bd3) { bd3 = s; bi3 = k0 + 1; }
        }
        __syncthreads();   // all reads of this buffer done before its refill
    }

    // ---- reduce: in-lane col pair, then quad (lanes share a row) ----
    amerge(bd0, bi0, bd1, bi1);         // row r
    amerge(bd2, bi2, bd3, bi3);         // row r+8
#pragma unroll
    for (int x = 1; x <= 2; x <<= 1) {
        float od = __shfl_xor_sync(0xffffffff, bd0, x);
        int   oi = __shfl_xor_sync(0xffffffff, bi0, x);
        amerge(bd0, bi0, od, oi);
        od = __shfl_xor_sync(0xffffffff, bd2, x);
        oi = __shfl_xor_sync(0xffffffff, bi2, x);
        amerge(bd2, bi2, od, oi);
    }
    if ((lane & 3) == 0) {
        sidx[w * 16 + (lane >> 2)]     = bi0;
        sidx[w * 16 + 8 + (lane >> 2)] = bi2;
    }
    __syncthreads();

    // ---- epilogue: gather, straight-through (bit-exact), loss ----
    float* ob = out + ((size_t)b << 18) + po;
    float lp = 0.0f;
#pragma unroll
    for (int j = 0; j < 32; ++j) {
        int i = t + j * 256;
        int c = i >> 7, px = i & 127;
        float q  = embed[sidx[px] * CDIM + c];
        float zv = zf[c * 128 + px];
        float d  = __fadd_rn(q, -zv);            // fl(z_q - z)
        ob[(c << 12) + px] = __fadd_rn(zv, d);   // fl(z + fl(z_q - z))
        lp += d * d;
    }
    red[t] = lp;
    __syncthreads();
    for (int s = TPB / 2; s > 0; s >>= 1) {
        if (t < s) red[t] += red[t + s];
        __syncthreads();
    }
    if (t == 0 && out_size > OUT_Q)
        atomicAdd(&out[OUT_Q], red[0] * (1.25f / (float)OUT_Q));
}

extern "C" void kernel_launch(void* const* d_in, const int* in_sizes, int n_in,
                              void* d_out, int out_size) {
    const float* z     = (const float*)d_in[0];
    const float* embed = (const float*)d_in[1];
    float* out = (float*)d_out;

    static int configured = 0;
    if (!configured) {
        cudaFuncSetAttribute(vq_main, cudaFuncAttributeMaxDynamicSharedMemorySize,
                             SM_TOT);
        configured = 1;
    }

    vq_pre<<<4, 256>>>(embed, out, out_size);
    vq_main<<<NPX / MPX, TPB, SM_TOT>>>(z, embed, out, out_size);
}

// round 8
// speedup vs baseline: 5.6837x; 1.0206x over previous
#include <cuda_runtime.h>
#include <cuda_fp16.h>
#include <cstdint>

// VectorQuantizer via mma.sync (HMMA) fp16 3-product split-GEMM,
// double-buffered cp.async staging, 3 independent accumulator chains.
// z [16,64,64,64] f32, embed [1024,64] f32.
// out[0..4194303] = z_q_st, out[4194304] = loss.

#define CDIM   64
#define NPX    65536
#define OUT_Q  4194304
#define KTOT   1024
#define TPB    256
#define MPX    128         // pixels per CTA
#define CHK    64          // codes per chunk (double-buffered)
#define NCHUNK 16
#define NGRP   8           // 8-code groups per chunk
#define ROWB   144         // padded row bytes -> conflict-free ldmatrix

// ---- smem byte offsets ----
#define SM_ZH   0                         // [128 px][72 halves] 18432
#define SM_ZL   18432
#define SM_EB   36864                     // 2 bufs x {EH 9216, EL 9216} = 36864
#define SM_ZF   73728                     // [64 c][128 px] f32  32768
#define SM_EE   106496                    // [1024] f32
#define SM_ZZ   110592                    // [128] f32
#define SM_IDX  111104                    // [128] int
#define SM_RED  111616                    // [256] f32
#define SM_TOT  112640
#define EBUF(buf) (SM_EB + (buf) * 18432)

__device__ uint4 g_ebh[KTOT * 8];   // fp16(1024*e)  [1024][64] halves
__device__ uint4 g_ebl[KTOT * 8];   // fp16 residual
__device__ float g_ee[KTOT];

__device__ __forceinline__ uint32_t smem_u32(const void* p) {
    uint32_t a;
    asm("{ .reg .u64 t; cvta.to.shared.u64 t, %1; cvt.u32.u64 %0, t; }"
        : "=r"(a) : "l"(p));
    return a;
}
__device__ __forceinline__ void ldsm4(uint32_t& r0, uint32_t& r1, uint32_t& r2,
                                      uint32_t& r3, uint32_t addr) {
    asm volatile("ldmatrix.sync.aligned.m8n8.x4.shared.b16 {%0,%1,%2,%3}, [%4];"
                 : "=r"(r0), "=r"(r1), "=r"(r2), "=r"(r3) : "r"(addr));
}
__device__ __forceinline__ void mma16816(float& d0, float& d1, float& d2, float& d3,
                                         uint32_t a0, uint32_t a1, uint32_t a2,
                                         uint32_t a3, uint32_t b0, uint32_t b1) {
    asm volatile(
        "mma.sync.aligned.m16n8k16.row.col.f32.f16.f16.f32 "
        "{%0,%1,%2,%3}, {%4,%5,%6,%7}, {%8,%9}, {%0,%1,%2,%3};"
        : "+f"(d0), "+f"(d1), "+f"(d2), "+f"(d3)
        : "r"(a0), "r"(a1), "r"(a2), "r"(a3), "r"(b0), "r"(b1));
}
__device__ __forceinline__ void amerge(float& d, int& i, float d2, int i2) {
    if (d2 < d || (d2 == d && i2 < i)) { d = d2; i = i2; }
}
#define CPA16(s, g) \
    asm volatile("cp.async.cg.shared.global [%0], [%1], 16;" \
                 :: "r"(s), "l"(g) : "memory")
#define CPA_COMMIT() asm volatile("cp.async.commit_group;" ::: "memory")
#define CPA_WAIT0()  asm volatile("cp.async.wait_group 0;" ::: "memory")

// ---------------- precompute: split codebook, ee ----------------
__global__ void vq_pre(const float* __restrict__ embed, float* out, int out_size) {
    int k = blockIdx.x * blockDim.x + threadIdx.x;
    if (k == 0 && out_size > OUT_Q) out[OUT_Q] = 0.0f;
    if (k >= KTOT) return;
    const float* e = embed + k * CDIM;
    __half2* eh = (__half2*)g_ebh;
    __half2* el = (__half2*)g_ebl;
    float s = 0.0f;
#pragma unroll
    for (int c = 0; c < CDIM; c += 2) {
        float v0 = e[c], v1 = e[c + 1];
        s = __fadd_rn(s, __fmul_rn(v0, v0));
        s = __fadd_rn(s, __fmul_rn(v1, v1));
        float w0 = v0 * 1024.0f, w1 = v1 * 1024.0f;   // exact scaling
        __half h0 = __float2half_rn(w0);
        __half h1 = __float2half_rn(w1);
        __half l0 = __float2half_rn(w0 - __half2float(h0));
        __half l1 = __float2half_rn(w1 - __half2float(h1));
        eh[k * 32 + (c >> 1)] = __halves2half2(h0, h1);
        el[k * 32 + (c >> 1)] = __halves2half2(l0, l1);
    }
    g_ee[k] = s;
}

// ---------------- main kernel ----------------
__global__ __launch_bounds__(TPB, 2)
void vq_main(const float* __restrict__ z,
             const float* __restrict__ embed,
             float* __restrict__ out, int out_size)
{
    extern __shared__ unsigned char smem[];
    const uint32_t sb = smem_u32(smem);
    float* zf  = (float*)(smem + SM_ZF);
    float* ee  = (float*)(smem + SM_EE);
    float* szz = (float*)(smem + SM_ZZ);
    int*   sidx = (int*)(smem + SM_IDX);
    float* red = (float*)(smem + SM_RED);

    const int t    = threadIdx.x;
    const int lane = t & 31;
    const int w    = t >> 5;              // warp 0..7: rows w*16..w*16+15

    const int base = blockIdx.x * MPX;
    const int b    = base >> 12;
    const int po   = base & 4095;
    const float* zb = z + ((size_t)b << 18) + po;

    // ---- stage chunk 0 immediately (overlap with z-tile work) ----
    {
        const uint4* srcH = g_ebh;
        const uint4* srcL = g_ebl;
#pragma unroll
        for (int j = 0; j < 2; ++j) {
            int i = t + j * 256;               // 512 uint4 per tier
            int row = i >> 3, q = i & 7;
            uint32_t off = (uint32_t)(row * ROWB + q * 16);
            CPA16(sb + EBUF(0) + off,        srcH + i);
            CPA16(sb + EBUF(0) + 9216 + off, srcL + i);
        }
        CPA_COMMIT();
    }

    // ---- load z tile (coalesced) + ee ----
#pragma unroll
    for (int j = 0; j < 32; ++j) {
        int i = t + j * 256;
        int c = i >> 7, px = i & 127;
        zf[c * 128 + px] = zb[(c << 12) + px];
    }
#pragma unroll
    for (int j = 0; j < 4; ++j) ee[t + j * 256] = g_ee[t + j * 256];
    __syncthreads();

    // ---- zz per pixel (reference rounding: sequential fp32) ----
    if (t < 128) {
        float s = 0.0f;
#pragma unroll
        for (int c = 0; c < CDIM; ++c) {
            float v = zf[c * 128 + t];
            s = __fadd_rn(s, __fmul_rn(v, v));
        }
        szz[t] = s;
    }

    // ---- split z into zh/zl fp16 tiles [px][72] ----
    {
        __half* zhp = (__half*)(smem + SM_ZH);
        __half* zlp = (__half*)(smem + SM_ZL);
#pragma unroll
        for (int j = 0; j < 32; ++j) {
            int i = t + j * 256;
            int c = i >> 7, px = i & 127;
            float v = zf[c * 128 + px];
            __half h = __float2half_rn(v);
            __half l = __float2half_rn(v - __half2float(h));
            zhp[px * 72 + c] = h;
            zlp[px * 72 + c] = l;
        }
    }
    __syncthreads();

    // ---- A fragments (register resident): 4 ksteps x {zh, zl} ----
    uint32_t aH[4][4], aL[4][4];
    {
        const int m    = lane >> 3;
        const int arow = w * 16 + (m & 1) * 8 + (lane & 7);
        const int coff = (m >> 1) * 16;
        uint32_t adH = sb + SM_ZH + arow * ROWB + coff;
        uint32_t adL = sb + SM_ZL + arow * ROWB + coff;
#pragma unroll
        for (int ks = 0; ks < 4; ++ks) {
            ldsm4(aH[ks][0], aH[ks][1], aH[ks][2], aH[ks][3], adH + ks * 32);
            ldsm4(aL[ks][0], aL[ks][1], aL[ks][2], aL[ks][3], adL + ks * 32);
        }
    }

    const float zzr0 = szz[w * 16 + (lane >> 2)];
    const float zzr8 = szz[w * 16 + 8 + (lane >> 2)];

    float bd0 = 3.4e38f, bd1 = 3.4e38f, bd2 = 3.4e38f, bd3 = 3.4e38f;
    int   bi0 = 0, bi1 = 0, bi2 = 0, bi3 = 0;

    const uint32_t blane = (lane & 7) * ROWB + (lane >> 3) * 16;
    const int cql = 2 * (lane & 3);

    for (int ch = 0; ch < NCHUNK; ++ch) {
        const int buf = ch & 1;
        CPA_WAIT0();          // current buffer filled
        __syncthreads();      // all warps done with the other buffer

        // prefetch chunk ch+1 into the other buffer (hidden under compute)
        if (ch + 1 < NCHUNK) {
            const uint4* srcH = g_ebh + (ch + 1) * CHK * 8;
            const uint4* srcL = g_ebl + (ch + 1) * CHK * 8;
            const uint32_t db = sb + EBUF(buf ^ 1);
#pragma unroll
            for (int j = 0; j < 2; ++j) {
                int i = t + j * 256;
                int row = i >> 3, q = i & 7;
                uint32_t off = (uint32_t)(row * ROWB + q * 16);
                CPA16(db + off,        srcH + i);
                CPA16(db + 9216 + off, srcL + i);
            }
            CPA_COMMIT();
        }

        const uint32_t bH0 = sb + EBUF(buf) + blane;
        const uint32_t bL0 = bH0 + 9216;

        // ---- group loop with B-register double buffering ----
        uint32_t bh[2][8], bl[2][8];
        ldsm4(bh[0][0], bh[0][1], bh[0][2], bh[0][3], bH0);
        ldsm4(bh[0][4], bh[0][5], bh[0][6], bh[0][7], bH0 + 64);
        ldsm4(bl[0][0], bl[0][1], bl[0][2], bl[0][3], bL0);
        ldsm4(bl[0][4], bl[0][5], bl[0][6], bl[0][7], bL0 + 64);

#pragma unroll
        for (int g = 0; g < NGRP; ++g) {
            const int cur = g & 1, nxt = cur ^ 1;
            if (g + 1 < NGRP) {
                const uint32_t bo = (uint32_t)((g + 1) * 8 * ROWB);
                ldsm4(bh[nxt][0], bh[nxt][1], bh[nxt][2], bh[nxt][3], bH0 + bo);
                ldsm4(bh[nxt][4], bh[nxt][5], bh[nxt][6], bh[nxt][7], bH0 + bo + 64);
                ldsm4(bl[nxt][0], bl[nxt][1], bl[nxt][2], bl[nxt][3], bL0 + bo);
                ldsm4(bl[nxt][4], bl[nxt][5], bl[nxt][6], bl[nxt][7], bL0 + bo + 64);
            }

            // 12 MMAs: 3 independent chains of 4 (aH*bh, aH*bl, aL*bh),
            // interleaved per kstep for 3-way ILP.
            float p0 = 0.f, p1 = 0.f, p2 = 0.f, p3 = 0.f;
            float q0 = 0.f, q1 = 0.f, q2 = 0.f, q3 = 0.f;
            float r0 = 0.f, r1 = 0.f, r2 = 0.f, r3 = 0.f;
#pragma unroll
            for (int ks = 0; ks < 4; ++ks) {
                mma16816(p0, p1, p2, p3, aH[ks][0], aH[ks][1], aH[ks][2], aH[ks][3],
                         bh[cur][2 * ks], bh[cur][2 * ks + 1]);
                mma16816(q0, q1, q2, q3, aH[ks][0], aH[ks][1], aH[ks][2], aH[ks][3],
                         bl[cur][2 * ks], bl[cur][2 * ks + 1]);
                mma16816(r0, r1, r2, r3, aL[ks][0], aL[ks][1], aL[ks][2], aL[ks][3],
                         bh[cur][2 * ks], bh[cur][2 * ks + 1]);
            }
            const float d0 = (p0 + q0) + r0, d1 = (p1 + q1) + r1;
            const float d2 = (p2 + q2) + r2, d3 = (p3 + q3) + r3;

            // fold: s = fl( fl(zz+ee) - dot'/512 ),  dot' = 1024*dot
            const int k0 = ch * CHK + g * 8 + cql;
            const float e0 = ee[k0], e1 = ee[k0 + 1];
            float s;
            s = __fmaf_rn(-(1.0f / 512.0f), d0, __fadd_rn(zzr0, e0));
            if (s < bd0) { bd0 = s; bi0 = k0; }
            s = __fmaf_rn(-(1.0f / 512.0f), d1, __fadd_rn(zzr0, e1));
            if (s < bd1) { bd1 = s; bi1 = k0 + 1; }
            s = __fmaf_rn(-(1.0f / 512.0f), d2, __fadd_rn(zzr8, e0));
            if (s < bd2) { bd2 = s; bi2 = k0; }
            s = __fmaf_rn(-(1.0f / 512.0f), d3, __fadd_rn(zzr8, e1));
            if (s < bd3) { bd3 = s; bi3 = k0 + 1; }
        }
        __syncthreads();   // all reads of this buffer done before its refill
    }

    // ---- reduce: in-lane col pair, then quad (lanes share a row) ----
    amerge(bd0, bi0, bd1, bi1);         // row r
    amerge(bd2, bi2, bd3, bi3);         // row r+8
#pragma unroll
    for (int x = 1; x <= 2; x <<= 1) {
        float od = __shfl_xor_sync(0xffffffff, bd0, x);
        int   oi = __shfl_xor_sync(0xffffffff, bi0, x);
        amerge(bd0, bi0, od, oi);
        od = __shfl_xor_sync(0xffffffff, bd2, x);
        oi = __shfl_xor_sync(0xffffffff, bi2, x);
        amerge(bd2, bi2, od, oi);
    }
    if ((lane & 3) == 0) {
        sidx[w * 16 + (lane >> 2)]     = bi0;
        sidx[w * 16 + 8 + (lane >> 2)] = bi2;
    }
    __syncthreads();

    // ---- epilogue: gather, straight-through (bit-exact), loss ----
    float* ob = out + ((size_t)b << 18) + po;
    float lp = 0.0f;
#pragma unroll
    for (int j = 0; j < 32; ++j) {
        int i = t + j * 256;
        int c = i >> 7, px = i & 127;
        float q  = embed[sidx[px] * CDIM + c];
        float zv = zf[c * 128 + px];
        float d  = __fadd_rn(q, -zv);            // fl(z_q - z)
        ob[(c << 12) + px] = __fadd_rn(zv, d);   // fl(z + fl(z_q - z))
        lp += d * d;
    }
    red[t] = lp;
    __syncthreads();
    for (int s = TPB / 2; s > 0; s >>= 1) {
        if (t < s) red[t] += red[t + s];
        __syncthreads();
    }
    if (t == 0 && out_size > OUT_Q)
        atomicAdd(&out[OUT_Q], red[0] * (1.25f / (float)OUT_Q));
}

extern "C" void kernel_launch(void* const* d_in, const int* in_sizes, int n_in,
                              void* d_out, int out_size) {
    const float* z     = (const float*)d_in[0];
    const float* embed = (const float*)d_in[1];
    float* out = (float*)d_out;

    static int configured = 0;
    if (!configured) {
        cudaFuncSetAttribute(vq_main, cudaFuncAttributeMaxDynamicSharedMemorySize,
                             SM_TOT);
        configured = 1;
    }

    vq_pre<<<4, 256>>>(embed, out, out_size);
    vq_main<<<NPX / MPX, TPB, SM_TOT>>>(z, embed, out, out_size);
}

// round 9
// speedup vs baseline: 6.6987x; 1.1786x over previous
#include <cuda_runtime.h>
#include <cuda_fp16.h>
#include <cstdint>

// VectorQuantizer via mma.sync (HMMA) fp16 3-product split-GEMM.
// Each warp owns 32 pixel rows (2 m16 tiles) sharing one B load -> half LDSM traffic.
// z [16,64,64,64] f32, embed [1024,64] f32.
// out[0..4194303] = z_q_st, out[4194304] = loss.

#define CDIM   64
#define NPX    65536
#define OUT_Q  4194304
#define KTOT   1024
#define TPB    256
#define MPX    256         // pixels per CTA
#define CHK    32          // codes per chunk (double-buffered)
#define NCHUNK 32
#define NGRP   4           // 8-code groups per chunk
#define ROWB   144         // padded row bytes -> conflict-free ldmatrix

// ---- smem byte offsets ----
#define SM_ZH   0                         // [256 px][72 halves] 36864
#define SM_ZL   36864
#define SM_EB   73728                     // 2 bufs x {EH 4608, EL 4608} = 18432
#define SM_EE   92160                     // [1024] f32
#define SM_ZZ   96256                     // [256] f32
#define SM_IDX  97280                     // [256] int
#define SM_RED  98304                     // [256] f32
#define SM_TOT  99328
#define EBUF(b) (SM_EB + (b) * 9216)

__device__ uint4 g_ebh[KTOT * 8];   // fp16(1024*e)  [1024][64] halves
__device__ uint4 g_ebl[KTOT * 8];   // fp16 residual
__device__ float g_ee[KTOT];

__device__ __forceinline__ uint32_t smem_u32(const void* p) {
    uint32_t a;
    asm("{ .reg .u64 t; cvta.to.shared.u64 t, %1; cvt.u32.u64 %0, t; }"
        : "=r"(a) : "l"(p));
    return a;
}
__device__ __forceinline__ void ldsm4(uint32_t& r0, uint32_t& r1, uint32_t& r2,
                                      uint32_t& r3, uint32_t addr) {
    asm volatile("ldmatrix.sync.aligned.m8n8.x4.shared.b16 {%0,%1,%2,%3}, [%4];"
                 : "=r"(r0), "=r"(r1), "=r"(r2), "=r"(r3) : "r"(addr));
}
__device__ __forceinline__ void mma16816(float& d0, float& d1, float& d2, float& d3,
                                         uint32_t a0, uint32_t a1, uint32_t a2,
                                         uint32_t a3, uint32_t b0, uint32_t b1) {
    asm volatile(
        "mma.sync.aligned.m16n8k16.row.col.f32.f16.f16.f32 "
        "{%0,%1,%2,%3}, {%4,%5,%6,%7}, {%8,%9}, {%0,%1,%2,%3};"
        : "+f"(d0), "+f"(d1), "+f"(d2), "+f"(d3)
        : "r"(a0), "r"(a1), "r"(a2), "r"(a3), "r"(b0), "r"(b1));
}
__device__ __forceinline__ void amerge(float& d, int& i, float d2, int i2) {
    if (d2 < d || (d2 == d && i2 < i)) { d = d2; i = i2; }
}
#define CPA16(s, g) \
    asm volatile("cp.async.cg.shared.global [%0], [%1], 16;" \
                 :: "r"(s), "l"(g) : "memory")
#define CPA_COMMIT() asm volatile("cp.async.commit_group;" ::: "memory")
#define CPA_WAIT0()  asm volatile("cp.async.wait_group 0;" ::: "memory")

// ---------------- precompute: split codebook, ee ----------------
__global__ void vq_pre(const float* __restrict__ embed, float* out, int out_size) {
    int k = blockIdx.x * blockDim.x + threadIdx.x;
    if (k == 0 && out_size > OUT_Q) out[OUT_Q] = 0.0f;
    if (k >= KTOT) return;
    const float* e = embed + k * CDIM;
    __half2* eh = (__half2*)g_ebh;
    __half2* el = (__half2*)g_ebl;
    float s = 0.0f;
#pragma unroll
    for (int c = 0; c < CDIM; c += 2) {
        float v0 = e[c], v1 = e[c + 1];
        s = __fadd_rn(s, __fmul_rn(v0, v0));
        s = __fadd_rn(s, __fmul_rn(v1, v1));
        float w0 = v0 * 1024.0f, w1 = v1 * 1024.0f;   // exact scaling
        __half h0 = __float2half_rn(w0);
        __half h1 = __float2half_rn(w1);
        __half l0 = __float2half_rn(w0 - __half2float(h0));
        __half l1 = __float2half_rn(w1 - __half2float(h1));
        eh[k * 32 + (c >> 1)] = __halves2half2(h0, h1);
        el[k * 32 + (c >> 1)] = __halves2half2(l0, l1);
    }
    g_ee[k] = s;
}

// ---------------- main kernel ----------------
__global__ __launch_bounds__(TPB, 2)
void vq_main(const float* __restrict__ z,
             const float* __restrict__ embed,
             float* __restrict__ out, int out_size)
{
    extern __shared__ unsigned char smem[];
    const uint32_t sb = smem_u32(smem);
    float* ee  = (float*)(smem + SM_EE);
    float* szz = (float*)(smem + SM_ZZ);
    int*   sidx = (int*)(smem + SM_IDX);
    float* red = (float*)(smem + SM_RED);

    const int t    = threadIdx.x;
    const int lane = t & 31;
    const int w    = t >> 5;              // warp 0..7: rows w*32..w*32+31

    const int base = blockIdx.x * MPX;
    const int b    = base >> 12;
    const int po   = base & 4095;
    const float* zb = z + ((size_t)b << 18) + po;

    // ---- stage chunk 0 immediately ----
    {
        uint32_t off = (uint32_t)((t >> 3) * ROWB + (t & 7) * 16);
        CPA16(sb + EBUF(0) + off,        g_ebh + t);
        CPA16(sb + EBUF(0) + 4608 + off, g_ebl + t);
        CPA_COMMIT();
    }

    // ---- ee table ----
#pragma unroll
    for (int j = 0; j < 4; ++j) ee[t + j * 256] = g_ee[t + j * 256];

    // ---- load z column for my pixel (px = t): split + zz in one pass ----
    {
        __half* zhp = (__half*)(smem + SM_ZH) + t * 72;
        __half* zlp = (__half*)(smem + SM_ZL) + t * 72;
        float s = 0.0f;
#pragma unroll
        for (int c = 0; c < CDIM; ++c) {
            float v = zb[(c << 12) + t];
            s = __fadd_rn(s, __fmul_rn(v, v));    // reference rounding, sequential
            __half h = __float2half_rn(v);
            __half l = __float2half_rn(v - __half2float(h));
            zhp[c] = h;
            zlp[c] = l;
        }
        szz[t] = s;
    }
    __syncthreads();

    // ---- A fragments (register resident): 2 tiles x 4 ksteps x {zh, zl} ----
    uint32_t aH[2][4][4], aL[2][4][4];
    {
        const int m    = lane >> 3;
        const int coff = (m >> 1) * 16;
#pragma unroll
        for (int tl = 0; tl < 2; ++tl) {
            const int arow = w * 32 + tl * 16 + (m & 1) * 8 + (lane & 7);
            uint32_t adH = sb + SM_ZH + arow * ROWB + coff;
            uint32_t adL = sb + SM_ZL + arow * ROWB + coff;
#pragma unroll
            for (int ks = 0; ks < 4; ++ks) {
                ldsm4(aH[tl][ks][0], aH[tl][ks][1], aH[tl][ks][2], aH[tl][ks][3],
                      adH + ks * 32);
                ldsm4(aL[tl][ks][0], aL[tl][ks][1], aL[tl][ks][2], aL[tl][ks][3],
                      adL + ks * 32);
            }
        }
    }

    const int rq = lane >> 2;
    const float zzA0 = szz[w * 32 + rq],      zzA8 = szz[w * 32 + 8 + rq];
    const float zzB0 = szz[w * 32 + 16 + rq], zzB8 = szz[w * 32 + 24 + rq];

    float bdA0 = 3.4e38f, bdA1 = 3.4e38f, bdA2 = 3.4e38f, bdA3 = 3.4e38f;
    float bdB0 = 3.4e38f, bdB1 = 3.4e38f, bdB2 = 3.4e38f, bdB3 = 3.4e38f;
    int biA0 = 0, biA1 = 0, biA2 = 0, biA3 = 0;
    int biB0 = 0, biB1 = 0, biB2 = 0, biB3 = 0;

    const uint32_t blane = (lane & 7) * ROWB + (lane >> 3) * 16;
    const int cql = 2 * (lane & 3);

    for (int ch = 0; ch < NCHUNK; ++ch) {
        const int buf = ch & 1;
        CPA_WAIT0();
        __syncthreads();

        // prefetch chunk ch+1 into the other buffer
        if (ch + 1 < NCHUNK) {
            const uint4* srcH = g_ebh + (ch + 1) * CHK * 8;
            const uint4* srcL = g_ebl + (ch + 1) * CHK * 8;
            const uint32_t db = sb + EBUF(buf ^ 1);
            uint32_t off = (uint32_t)((t >> 3) * ROWB + (t & 7) * 16);
            CPA16(db + off,        srcH + t);
            CPA16(db + 4608 + off, srcL + t);
            CPA_COMMIT();
        }

        const uint32_t bH0 = sb + EBUF(buf) + blane;
        const uint32_t bL0 = bH0 + 4608;

#pragma unroll
        for (int g = 0; g < NGRP; ++g) {
            const uint32_t bo = (uint32_t)(g * 8 * ROWB);
            uint32_t bh[8], bl[8];
            ldsm4(bh[0], bh[1], bh[2], bh[3], bH0 + bo);
            ldsm4(bh[4], bh[5], bh[6], bh[7], bH0 + bo + 64);
            ldsm4(bl[0], bl[1], bl[2], bl[3], bL0 + bo);
            ldsm4(bl[4], bl[5], bl[6], bl[7], bL0 + bo + 64);

            const int k0 = ch * CHK + g * 8 + cql;
            const float e0 = ee[k0], e1 = ee[k0 + 1];

            // ---- tile 0: 12 MMAs, 3 independent chains ----
            {
                float p0 = 0.f, p1 = 0.f, p2 = 0.f, p3 = 0.f;
                float q0 = 0.f, q1 = 0.f, q2 = 0.f, q3 = 0.f;
                float r0 = 0.f, r1 = 0.f, r2 = 0.f, r3 = 0.f;
#pragma unroll
                for (int ks = 0; ks < 4; ++ks) {
                    mma16816(p0, p1, p2, p3, aH[0][ks][0], aH[0][ks][1],
                             aH[0][ks][2], aH[0][ks][3], bh[2 * ks], bh[2 * ks + 1]);
                    mma16816(q0, q1, q2, q3, aH[0][ks][0], aH[0][ks][1],
                             aH[0][ks][2], aH[0][ks][3], bl[2 * ks], bl[2 * ks + 1]);
                    mma16816(r0, r1, r2, r3, aL[0][ks][0], aL[0][ks][1],
                             aL[0][ks][2], aL[0][ks][3], bh[2 * ks], bh[2 * ks + 1]);
                }
                const float d0 = (p0 + q0) + r0, d1 = (p1 + q1) + r1;
                const float d2 = (p2 + q2) + r2, d3 = (p3 + q3) + r3;
                float s;
                s = __fmaf_rn(-(1.0f / 512.0f), d0, __fadd_rn(zzA0, e0));
                if (s < bdA0) { bdA0 = s; biA0 = k0; }
                s = __fmaf_rn(-(1.0f / 512.0f), d1, __fadd_rn(zzA0, e1));
                if (s < bdA1) { bdA1 = s; biA1 = k0 + 1; }
                s = __fmaf_rn(-(1.0f / 512.0f), d2, __fadd_rn(zzA8, e0));
                if (s < bdA2) { bdA2 = s; biA2 = k0; }
                s = __fmaf_rn(-(1.0f / 512.0f), d3, __fadd_rn(zzA8, e1));
                if (s < bdA3) { bdA3 = s; biA3 = k0 + 1; }
            }
            // ---- tile 1 ----
            {
                float p0 = 0.f, p1 = 0.f, p2 = 0.f, p3 = 0.f;
                float q0 = 0.f, q1 = 0.f, q2 = 0.f, q3 = 0.f;
                float r0 = 0.f, r1 = 0.f, r2 = 0.f, r3 = 0.f;
#pragma unroll
                for (int ks = 0; ks < 4; ++ks) {
                    mma16816(p0, p1, p2, p3, aH[1][ks][0], aH[1][ks][1],
                             aH[1][ks][2], aH[1][ks][3], bh[2 * ks], bh[2 * ks + 1]);
                    mma16816(q0, q1, q2, q3, aH[1][ks][0], aH[1][ks][1],
                             aH[1][ks][2], aH[1][ks][3], bl[2 * ks], bl[2 * ks + 1]);
                    mma16816(r0, r1, r2, r3, aL[1][ks][0], aL[1][ks][1],
                             aL[1][ks][2], aL[1][ks][3], bh[2 * ks], bh[2 * ks + 1]);
                }
                const float d0 = (p0 + q0) + r0, d1 = (p1 + q1) + r1;
                const float d2 = (p2 + q2) + r2, d3 = (p3 + q3) + r3;
                float s;
                s = __fmaf_rn(-(1.0f / 512.0f), d0, __fadd_rn(zzB0, e0));
                if (s < bdB0) { bdB0 = s; biB0 = k0; }
                s = __fmaf_rn(-(1.0f / 512.0f), d1, __fadd_rn(zzB0, e1));
                if (s < bdB1) { bdB1 = s; biB1 = k0 + 1; }
                s = __fmaf_rn(-(1.0f / 512.0f), d2, __fadd_rn(zzB8, e0));
                if (s < bdB2) { bdB2 = s; biB2 = k0; }
                s = __fmaf_rn(-(1.0f / 512.0f), d3, __fadd_rn(zzB8, e1));
                if (s < bdB3) { bdB3 = s; biB3 = k0 + 1; }
            }
        }
        __syncthreads();
    }

    // ---- reduce: in-lane col pair, then quad; per tile ----
    amerge(bdA0, biA0, bdA1, biA1);
    amerge(bdA2, biA2, bdA3, biA3);
    amerge(bdB0, biB0, bdB1, biB1);
    amerge(bdB2, biB2, bdB3, biB3);
#pragma unroll
    for (int x = 1; x <= 2; x <<= 1) {
        float od; int oi;
        od = __shfl_xor_sync(0xffffffff, bdA0, x);
        oi = __shfl_xor_sync(0xffffffff, biA0, x);
        amerge(bdA0, biA0, od, oi);
        od = __shfl_xor_sync(0xffffffff, bdA2, x);
        oi = __shfl_xor_sync(0xffffffff, biA2, x);
        amerge(bdA2, biA2, od, oi);
        od = __shfl_xor_sync(0xffffffff, bdB0, x);
        oi = __shfl_xor_sync(0xffffffff, biB0, x);
        amerge(bdB0, biB0, od, oi);
        od = __shfl_xor_sync(0xffffffff, bdB2, x);
        oi = __shfl_xor_sync(0xffffffff, biB2, x);
        amerge(bdB2, biB2, od, oi);
    }
    if ((lane & 3) == 0) {
        sidx[w * 32 + rq]          = biA0;
        sidx[w * 32 + 8 + rq]      = biA2;
        sidx[w * 32 + 16 + rq]     = biB0;
        sidx[w * 32 + 24 + rq]     = biB2;
    }
    __syncthreads();

    // ---- epilogue: gather, straight-through (bit-exact), loss; px = t ----
    float* ob = out + ((size_t)b << 18) + po;
    const float4* er4 = (const float4*)(embed + sidx[t] * CDIM);
    float lp = 0.0f;
#pragma unroll
    for (int j = 0; j < 16; ++j) {
        float4 qv = er4[j];
        int c = j * 4;
        float z0 = zb[((c + 0) << 12) + t];
        float z1 = zb[((c + 1) << 12) + t];
        float z2 = zb[((c + 2) << 12) + t];
        float z3 = zb[((c + 3) << 12) + t];
        float d0 = __fadd_rn(qv.x, -z0);
        float d1 = __fadd_rn(qv.y, -z1);
        float d2 = __fadd_rn(qv.z, -z2);
        float d3 = __fadd_rn(qv.w, -z3);
        ob[((c + 0) << 12) + t] = __fadd_rn(z0, d0);
        ob[((c + 1) << 12) + t] = __fadd_rn(z1, d1);
        ob[((c + 2) << 12) + t] = __fadd_rn(z2, d2);
        ob[((c + 3) << 12) + t] = __fadd_rn(z3, d3);
        lp += d0 * d0 + d1 * d1 + d2 * d2 + d3 * d3;
    }
    red[t] = lp;
    __syncthreads();
    for (int s = TPB / 2; s > 0; s >>= 1) {
        if (t < s) red[t] += red[t + s];
        __syncthreads();
    }
    if (t == 0 && out_size > OUT_Q)
        atomicAdd(&out[OUT_Q], red[0] * (1.25f / (float)OUT_Q));
}

extern "C" void kernel_launch(void* const* d_in, const int* in_sizes, int n_in,
                              void* d_out, int out_size) {
    const float* z     = (const float*)d_in[0];
    const float* embed = (const float*)d_in[1];
    float* out = (float*)d_out;

    static int configured = 0;
    if (!configured) {
        cudaFuncSetAttribute(vq_main, cudaFuncAttributeMaxDynamicSharedMemorySize,
                             SM_TOT);
        configured = 1;
    }

    vq_pre<<<4, 256>>>(embed, out, out_size);
    vq_main<<<NPX / MPX, TPB, SM_TOT>>>(z, embed, out, out_size);
}